// round 1
// baseline (speedup 1.0000x reference)
#include <cuda_runtime.h>
#include <math.h>

#define BSZ     4
#define LSEQ    4096
#define DMODEL  768
#define DSTATE  128
#define HEADDIM 64
#define DINNER  1536
#define NHEADS  24
#define DPROJ   3352       // 2*1536 + 2*128 + 24
#define CONVCH  1792       // 1536 + 2*128
#define EPSV    1e-5f
#define NBT     (BSZ*LSEQ) // 16384

// ---------------- scratch (static device globals: no runtime allocation) ----
__device__ float g_u  [(size_t)NBT * DMODEL];   //  50 MB
__device__ float g_zx [(size_t)NBT * DPROJ];    // 220 MB
__device__ float g_xbc[(size_t)NBT * CONVCH];   // 117 MB
__device__ float g_y  [(size_t)NBT * DINNER];   // 100 MB
__device__ float g_dA [NBT * NHEADS];
__device__ float g_dt [NBT * NHEADS];

// ---------------- helpers ---------------------------------------------------
__device__ __forceinline__ float block_reduce_sum(float v, float* red) {
    #pragma unroll
    for (int o = 16; o; o >>= 1) v += __shfl_down_sync(0xffffffffu, v, o);
    int lane = threadIdx.x & 31, wid = threadIdx.x >> 5;
    if (lane == 0) red[wid] = v;
    __syncthreads();
    int nw = blockDim.x >> 5;
    v = (threadIdx.x < nw) ? red[threadIdx.x] : 0.f;
    if (wid == 0) {
        #pragma unroll
        for (int o = 16; o; o >>= 1) v += __shfl_down_sync(0xffffffffu, v, o);
        if (lane == 0) red[0] = v;
    }
    __syncthreads();
    return red[0];
}

// ---------------- 1) LayerNorm ---------------------------------------------
__global__ void __launch_bounds__(256) ln_kernel(const float* __restrict__ x,
                                                 const float* __restrict__ w,
                                                 const float* __restrict__ b) {
    __shared__ float red[32];
    int row = blockIdx.x;
    const float* xr = x + (size_t)row * DMODEL;
    float v[3], s = 0.f, ss = 0.f;
    #pragma unroll
    for (int i = 0; i < 3; i++) {
        v[i] = xr[threadIdx.x + i * 256];
        s += v[i]; ss += v[i] * v[i];
    }
    float tot = block_reduce_sum(s, red);
    __syncthreads();
    float tot2 = block_reduce_sum(ss, red);
    float mu  = tot / DMODEL;
    float var = tot2 / DMODEL - mu * mu;
    float inv = rsqrtf(var + EPSV);
    float* ur = g_u + (size_t)row * DMODEL;
    #pragma unroll
    for (int i = 0; i < 3; i++) {
        int c = threadIdx.x + i * 256;
        ur[c] = (v[i] - mu) * inv * w[c] + b[c];
    }
}

// ---------------- SGEMM (fp32, 128x128x8 tile, 8x8/thread) ------------------
#define BM 128
#define BN 128
#define BK 8
__global__ void __launch_bounds__(256) sgemm_kernel(const float* __restrict__ A,
                                                    const float* __restrict__ B,
                                                    float* __restrict__ C,
                                                    const float* __restrict__ R,
                                                    int M, int N, int K) {
    __shared__ float As[BK][BM];
    __shared__ float Bs[BK][BN];
    int tid  = threadIdx.x;
    int row0 = blockIdx.y * BM;
    int col0 = blockIdx.x * BN;

    int arow = tid >> 1;            // 0..127
    int acol = (tid & 1) * 4;       // 0 or 4
    int brw  = tid >> 5;            // 0..7
    int bcl  = (tid & 31) * 4;      // 0..124
    int ty   = tid >> 4, tx = tid & 15;

    float acc[8][8];
    #pragma unroll
    for (int i = 0; i < 8; i++)
        #pragma unroll
        for (int j = 0; j < 8; j++) acc[i][j] = 0.f;

    const float* Aptr = A + (size_t)(row0 + arow) * K + acol;
    int gcol = col0 + bcl;

    for (int k0 = 0; k0 < K; k0 += BK) {
        float4 av = *(const float4*)(Aptr + k0);
        As[acol + 0][arow] = av.x;
        As[acol + 1][arow] = av.y;
        As[acol + 2][arow] = av.z;
        As[acol + 3][arow] = av.w;
        float4 bv = make_float4(0.f, 0.f, 0.f, 0.f);
        if (gcol < N) bv = *(const float4*)(B + (size_t)(k0 + brw) * N + gcol);
        *(float4*)&Bs[brw][bcl] = bv;
        __syncthreads();
        #pragma unroll
        for (int k = 0; k < BK; k++) {
            float a[8], bb[8];
            #pragma unroll
            for (int i = 0; i < 8; i++) a[i]  = As[k][ty * 8 + i];
            #pragma unroll
            for (int j = 0; j < 8; j++) bb[j] = Bs[k][tx * 8 + j];
            #pragma unroll
            for (int i = 0; i < 8; i++)
                #pragma unroll
                for (int j = 0; j < 8; j++)
                    acc[i][j] = fmaf(a[i], bb[j], acc[i][j]);
        }
        __syncthreads();
    }

    int cbase = col0 + tx * 8;
    if (cbase < N) {   // N % 8 == 0, so a thread's 8 cols are all-in or all-out
        #pragma unroll
        for (int i = 0; i < 8; i++) {
            int r = row0 + ty * 8 + i;
            float* Cp = C + (size_t)r * N + cbase;
            if (R) {
                const float* Rp = R + (size_t)r * N + cbase;
                #pragma unroll
                for (int j = 0; j < 8; j++) Cp[j] = acc[i][j] + Rp[j];
            } else {
                #pragma unroll
                for (int j = 0; j < 8; j++) Cp[j] = acc[i][j];
            }
        }
    }
}

// ---------------- 3) causal depthwise conv (K=4) + SiLU ---------------------
__global__ void conv_kernel(const float* __restrict__ cw, const float* __restrict__ cb) {
    int id = blockIdx.x * blockDim.x + threadIdx.x;
    if (id >= NBT * CONVCH) return;
    int c  = id % CONVCH;
    int bt = id / CONVCH;
    int t  = bt % LSEQ;
    int b  = bt / LSEQ;
    const float* src = g_zx + (size_t)(b * LSEQ) * DPROJ + DINNER + c;
    float acc = cb[c];
    #pragma unroll
    for (int k = 0; k < 4; k++) {
        int ti = t - 3 + k;
        if (ti >= 0) acc = fmaf(cw[c * 4 + k], src[(size_t)ti * DPROJ], acc);
    }
    g_xbc[id] = acc / (1.f + expf(-acc));   // SiLU
}

// ---------------- 4) dt softplus + dA ---------------------------------------
__global__ void dt_kernel(const float* __restrict__ dt_bias, const float* __restrict__ A_log) {
    int id = blockIdx.x * blockDim.x + threadIdx.x;
    if (id >= NBT * NHEADS) return;
    int h  = id % NHEADS;
    int bt = id / NHEADS;
    float v  = g_zx[(size_t)bt * DPROJ + (DPROJ - NHEADS) + h] + dt_bias[h];
    float sp = (v > 20.f) ? v : log1pf(expf(v));
    g_dt[id] = sp;
    g_dA[id] = expf(-expf(A_log[h]) * sp);
}

// ---------------- 5) selective scan (one block per (b,h)) -------------------
// 512 threads: p = tid/8 (head row), sub = tid%8, 16 states (n) per thread.
__global__ void __launch_bounds__(512) scan_kernel(const float* __restrict__ Dv) {
    int blk = blockIdx.x;
    int b = blk / NHEADS, h = blk % NHEADS;
    int tid = threadIdx.x;
    int p = tid >> 3, sub = tid & 7, n0 = sub * 16;

    const float* Bb  = g_xbc + (size_t)(b * LSEQ) * CONVCH + DINNER + n0;
    const float* Cb  = Bb + DSTATE;
    const float* xb  = g_xbc + (size_t)(b * LSEQ) * CONVCH + h * HEADDIM + p;
    const float* dAb = g_dA + b * LSEQ * NHEADS + h;
    const float* dtb = g_dt + b * LSEQ * NHEADS + h;
    float Dh = Dv[h];
    float* yb = g_y + (size_t)(b * LSEQ) * DINNER + h * HEADDIM + p;

    float hs[16];
    #pragma unroll
    for (int i = 0; i < 16; i++) hs[i] = 0.f;

    // software-prefetched step inputs (1 ahead) so the serial chain is
    // FMA-issue-bound rather than L2-latency-bound
    float4 nB[4], nC[4];
    float ndA, ndt, nx;
    #pragma unroll
    for (int i = 0; i < 4; i++) {
        nB[i] = *(const float4*)(Bb + i * 4);
        nC[i] = *(const float4*)(Cb + i * 4);
    }
    ndA = dAb[0]; ndt = dtb[0]; nx = xb[0];

    for (int t = 0; t < LSEQ; t++) {
        float4 cB[4], cC[4];
        #pragma unroll
        for (int i = 0; i < 4; i++) { cB[i] = nB[i]; cC[i] = nC[i]; }
        float cdA = ndA, cdt = ndt, cx = nx;
        if (t + 1 < LSEQ) {
            const float* B1 = Bb + (size_t)(t + 1) * CONVCH;
            const float* C1 = Cb + (size_t)(t + 1) * CONVCH;
            #pragma unroll
            for (int i = 0; i < 4; i++) {
                nB[i] = *(const float4*)(B1 + i * 4);
                nC[i] = *(const float4*)(C1 + i * 4);
            }
            ndA = dAb[(t + 1) * NHEADS];
            ndt = dtb[(t + 1) * NHEADS];
            nx  = xb[(size_t)(t + 1) * CONVCH];
        }
        float dtx = cdt * cx;
        float acc = 0.f;
        #pragma unroll
        for (int i = 0; i < 4; i++) {
            float*       hv = hs + i * 4;
            const float* bp = (const float*)&cB[i];
            const float* cp = (const float*)&cC[i];
            #pragma unroll
            for (int j = 0; j < 4; j++) {
                hv[j] = fmaf(cdA, hv[j], dtx * bp[j]);
                acc   = fmaf(hv[j], cp[j], acc);
            }
        }
        acc += __shfl_down_sync(0xffffffffu, acc, 4, 8);
        acc += __shfl_down_sync(0xffffffffu, acc, 2, 8);
        acc += __shfl_down_sync(0xffffffffu, acc, 1, 8);
        if (sub == 0) yb[(size_t)t * DINNER] = acc + Dh * cx;
    }
}

// ---------------- 6) gate (y * silu(z)) + RMSNorm ---------------------------
__global__ void __launch_bounds__(256) gate_kernel(const float* __restrict__ norm_w) {
    __shared__ float red[32];
    int row = blockIdx.x;
    const float* zr = g_zx + (size_t)row * DPROJ;    // z = first 1536 cols
    float* yr = g_y + (size_t)row * DINNER;
    float g[6], ss = 0.f;
    #pragma unroll
    for (int i = 0; i < 6; i++) {
        int c = threadIdx.x + i * 256;
        float z = zr[c];
        float y = yr[c];
        float gv = y * (z / (1.f + expf(-z)));
        g[i] = gv;
        ss += gv * gv;
    }
    float tot = block_reduce_sum(ss, red);
    float inv = rsqrtf(tot / DINNER + EPSV);
    #pragma unroll
    for (int i = 0; i < 6; i++) {
        int c = threadIdx.x + i * 256;
        yr[c] = g[i] * inv * norm_w[c];
    }
}

// ---------------- launcher ---------------------------------------------------
extern "C" void kernel_launch(void* const* d_in, const int* in_sizes, int n_in,
                              void* d_out, int out_size) {
    const float* x       = (const float*)d_in[0];
    const float* ln_w    = (const float*)d_in[1];
    const float* ln_b    = (const float*)d_in[2];
    const float* W_in    = (const float*)d_in[3];
    const float* conv_w  = (const float*)d_in[4];
    const float* conv_b  = (const float*)d_in[5];
    const float* A_log   = (const float*)d_in[6];
    const float* Dv      = (const float*)d_in[7];
    const float* dt_bias = (const float*)d_in[8];
    const float* norm_w  = (const float*)d_in[9];
    const float* W_out   = (const float*)d_in[10];
    float* out = (float*)d_out;

    float *pu, *pzx, *py;
    cudaGetSymbolAddress((void**)&pu,  g_u);
    cudaGetSymbolAddress((void**)&pzx, g_zx);
    cudaGetSymbolAddress((void**)&py,  g_y);

    ln_kernel<<<NBT, 256>>>(x, ln_w, ln_b);

    dim3 g1((DPROJ + BN - 1) / BN, NBT / BM);   // 27 x 128
    sgemm_kernel<<<g1, 256>>>(pu, W_in, pzx, nullptr, NBT, DPROJ, DMODEL);

    conv_kernel<<<(NBT * CONVCH + 255) / 256, 256>>>(conv_w, conv_b);
    dt_kernel<<<(NBT * NHEADS + 255) / 256, 256>>>(dt_bias, A_log);

    scan_kernel<<<BSZ * NHEADS, 512>>>(Dv);

    gate_kernel<<<NBT, 256>>>(norm_w);

    dim3 g2(DMODEL / BN, NBT / BM);             // 6 x 128
    sgemm_kernel<<<g2, 256>>>(py, W_out, out, x, NBT, DMODEL, DINNER);
}

// round 4
// speedup vs baseline: 1.2753x; 1.2753x over previous
#include <cuda_runtime.h>
#include <math.h>
#include <mma.h>

using namespace nvcuda;

#define BSZ     4
#define LSEQ    4096
#define DMODEL  768
#define DSTATE  128
#define HEADDIM 64
#define DINNER  1536
#define NHEADS  24
#define DPROJ   3352       // 2*1536 + 2*128 + 24 (logical)
#define DPROJP  3456       // padded to 27*128 so GEMM1 stores need no N-guard
#define CONVCH  1792       // 1536 + 2*128
#define EPSV    1e-5f
#define NBT     (BSZ*LSEQ) // 16384

// ---------------- scratch (static device globals: no runtime allocation) ----
__device__ float g_u  [(size_t)NBT * DMODEL];
__device__ float g_zx [(size_t)NBT * DPROJP];   // padded width
__device__ float g_xbc[(size_t)NBT * CONVCH];
__device__ float g_y  [(size_t)NBT * DINNER];
__device__ float g_dA [NBT * NHEADS];
__device__ float g_dt [NBT * NHEADS];

// ---------------- helpers ---------------------------------------------------
__device__ __forceinline__ float block_reduce_sum(float v, float* red) {
    #pragma unroll
    for (int o = 16; o; o >>= 1) v += __shfl_down_sync(0xffffffffu, v, o);
    int lane = threadIdx.x & 31, wid = threadIdx.x >> 5;
    if (lane == 0) red[wid] = v;
    __syncthreads();
    int nw = blockDim.x >> 5;
    v = (threadIdx.x < nw) ? red[threadIdx.x] : 0.f;
    if (wid == 0) {
        #pragma unroll
        for (int o = 16; o; o >>= 1) v += __shfl_down_sync(0xffffffffu, v, o);
        if (lane == 0) red[0] = v;
    }
    __syncthreads();
    return red[0];
}

// ---------------- 1) LayerNorm ---------------------------------------------
__global__ void __launch_bounds__(256) ln_kernel(const float* __restrict__ x,
                                                 const float* __restrict__ w,
                                                 const float* __restrict__ b) {
    __shared__ float red[32];
    int row = blockIdx.x;
    const float* xr = x + (size_t)row * DMODEL;
    float v[3], s = 0.f, ss = 0.f;
    #pragma unroll
    for (int i = 0; i < 3; i++) {
        v[i] = xr[threadIdx.x + i * 256];
        s += v[i]; ss += v[i] * v[i];
    }
    float tot = block_reduce_sum(s, red);
    __syncthreads();
    float tot2 = block_reduce_sum(ss, red);
    float mu  = tot / DMODEL;
    float var = tot2 / DMODEL - mu * mu;
    float inv = rsqrtf(var + EPSV);
    float* ur = g_u + (size_t)row * DMODEL;
    #pragma unroll
    for (int i = 0; i < 3; i++) {
        int c = threadIdx.x + i * 256;
        ur[c] = (v[i] - mu) * inv * w[c] + b[c];
    }
}

// ---------------- TF32 tensor-core GEMM (128x128 block tile, BK=32) ---------
// 256 threads = 8 warps in a 4x2 grid; each warp owns a 32x64 tile = 2x4 wmma
// m16n16k8 accumulators. A row-major [M,K], B row-major [K,N]; C stride NP.
// GUARD: zero-fill B columns >= N (N not multiple of 128). Store is unguarded
// (C buffer padded to NP, NP % 128 == 0 region covered by grid).
// RESID: C = A*B + R (R stride NP).
template<bool GUARD, bool RESID>
__global__ void __launch_bounds__(256) gemm_tf32(const float* __restrict__ A,
                                                 const float* __restrict__ B,
                                                 float* __restrict__ C,
                                                 const float* __restrict__ R,
                                                 int M, int N, int NP, int K) {
    __shared__ float As[128][40];   // pad 32->40 to dodge bank conflicts
    __shared__ float Bs[32][136];   // pad 128->136

    int tid  = threadIdx.x;
    int warp = tid >> 5;
    int wm   = warp >> 1;           // 0..3
    int wn   = warp & 1;            // 0..1
    int row0 = blockIdx.y * 128;
    int col0 = blockIdx.x * 128;

    wmma::fragment<wmma::accumulator, 16, 16, 8, float> acc[2][4];
    #pragma unroll
    for (int i = 0; i < 2; i++)
        #pragma unroll
        for (int j = 0; j < 4; j++) wmma::fill_fragment(acc[i][j], 0.f);

    int ar = tid >> 3;              // 0..31 (A row group base)
    int ac = (tid & 7) * 4;         // 0..28 (A col)

    for (int k0 = 0; k0 < K; k0 += 32) {
        // ---- A tile 128x32 (4 float4 per thread) ----
        #pragma unroll
        for (int i = 0; i < 4; i++) {
            int r = ar + i * 32;
            float4 v = *(const float4*)(A + (size_t)(row0 + r) * K + k0 + ac);
            v.x = wmma::__float_to_tf32(v.x);
            v.y = wmma::__float_to_tf32(v.y);
            v.z = wmma::__float_to_tf32(v.z);
            v.w = wmma::__float_to_tf32(v.w);
            *(float4*)&As[r][ac] = v;
        }
        // ---- B tile 32x128 (4 float4 per thread) ----
        #pragma unroll
        for (int i = 0; i < 4; i++) {
            int chunk = tid + 256 * i;
            int r = chunk >> 5;           // 0..31
            int c = (chunk & 31) * 4;     // 0..124
            float4 v = make_float4(0.f, 0.f, 0.f, 0.f);
            if (!GUARD || (col0 + c) < N)   // N % 4 == 0: float4 all-in/out
                v = *(const float4*)(B + (size_t)(k0 + r) * N + col0 + c);
            v.x = wmma::__float_to_tf32(v.x);
            v.y = wmma::__float_to_tf32(v.y);
            v.z = wmma::__float_to_tf32(v.z);
            v.w = wmma::__float_to_tf32(v.w);
            *(float4*)&Bs[r][c] = v;
        }
        __syncthreads();

        #pragma unroll
        for (int kk = 0; kk < 32; kk += 8) {
            wmma::fragment<wmma::matrix_a, 16, 16, 8, wmma::precision::tf32, wmma::row_major> af[2];
            wmma::fragment<wmma::matrix_b, 16, 16, 8, wmma::precision::tf32, wmma::row_major> bf[4];
            #pragma unroll
            for (int i = 0; i < 2; i++)
                wmma::load_matrix_sync(af[i], &As[wm * 32 + i * 16][kk], 40);
            #pragma unroll
            for (int j = 0; j < 4; j++)
                wmma::load_matrix_sync(bf[j], &Bs[kk][wn * 64 + j * 16], 136);
            #pragma unroll
            for (int i = 0; i < 2; i++)
                #pragma unroll
                for (int j = 0; j < 4; j++)
                    wmma::mma_sync(acc[i][j], af[i], bf[j], acc[i][j]);
        }
        __syncthreads();
    }

    // ---- epilogue ----
    #pragma unroll
    for (int i = 0; i < 2; i++)
        #pragma unroll
        for (int j = 0; j < 4; j++) {
            int r = row0 + wm * 32 + i * 16;
            int c = col0 + wn * 64 + j * 16;
            float* Cp = C + (size_t)r * NP + c;
            if (RESID) {
                wmma::fragment<wmma::accumulator, 16, 16, 8, float> rf;
                wmma::load_matrix_sync(rf, R + (size_t)r * NP + c, NP, wmma::mem_row_major);
                #pragma unroll
                for (int e = 0; e < rf.num_elements; e++) acc[i][j].x[e] += rf.x[e];
            }
            wmma::store_matrix_sync(Cp, acc[i][j], NP, wmma::mem_row_major);
        }
}

// ---------------- 3) causal depthwise conv (K=4) + SiLU ---------------------
__global__ void conv_kernel(const float* __restrict__ cw, const float* __restrict__ cb) {
    int id = blockIdx.x * blockDim.x + threadIdx.x;
    if (id >= NBT * CONVCH) return;
    int c  = id % CONVCH;
    int bt = id / CONVCH;
    int t  = bt % LSEQ;
    int b  = bt / LSEQ;
    const float* src = g_zx + (size_t)(b * LSEQ) * DPROJP + DINNER + c;
    float acc = cb[c];
    #pragma unroll
    for (int k = 0; k < 4; k++) {
        int ti = t - 3 + k;
        if (ti >= 0) acc = fmaf(cw[c * 4 + k], src[(size_t)ti * DPROJP], acc);
    }
    g_xbc[id] = acc / (1.f + expf(-acc));   // SiLU
}

// ---------------- 4) dt softplus + dA ---------------------------------------
__global__ void dt_kernel(const float* __restrict__ dt_bias, const float* __restrict__ A_log) {
    int id = blockIdx.x * blockDim.x + threadIdx.x;
    if (id >= NBT * NHEADS) return;
    int h  = id % NHEADS;
    int bt = id / NHEADS;
    float v  = g_zx[(size_t)bt * DPROJP + (DINNER + DINNER + 2 * DSTATE) + h] + dt_bias[h];
    float sp = (v > 20.f) ? v : log1pf(expf(v));
    g_dt[id] = sp;
    g_dA[id] = expf(-expf(A_log[h]) * sp);
}

// ---------------- 5) selective scan (one block per (b,h)) -------------------
__global__ void __launch_bounds__(512) scan_kernel(const float* __restrict__ Dv) {
    int blk = blockIdx.x;
    int b = blk / NHEADS, h = blk % NHEADS;
    int tid = threadIdx.x;
    int p = tid >> 3, sub = tid & 7, n0 = sub * 16;

    const float* Bb  = g_xbc + (size_t)(b * LSEQ) * CONVCH + DINNER + n0;
    const float* Cb  = Bb + DSTATE;
    const float* xb  = g_xbc + (size_t)(b * LSEQ) * CONVCH + h * HEADDIM + p;
    const float* dAb = g_dA + b * LSEQ * NHEADS + h;
    const float* dtb = g_dt + b * LSEQ * NHEADS + h;
    float Dh = Dv[h];
    float* yb = g_y + (size_t)(b * LSEQ) * DINNER + h * HEADDIM + p;

    float hs[16];
    #pragma unroll
    for (int i = 0; i < 16; i++) hs[i] = 0.f;

    float4 nB[4], nC[4];
    float ndA, ndt, nx;
    #pragma unroll
    for (int i = 0; i < 4; i++) {
        nB[i] = *(const float4*)(Bb + i * 4);
        nC[i] = *(const float4*)(Cb + i * 4);
    }
    ndA = dAb[0]; ndt = dtb[0]; nx = xb[0];

    for (int t = 0; t < LSEQ; t++) {
        float4 cB[4], cC[4];
        #pragma unroll
        for (int i = 0; i < 4; i++) { cB[i] = nB[i]; cC[i] = nC[i]; }
        float cdA = ndA, cdt = ndt, cx = nx;
        if (t + 1 < LSEQ) {
            const float* B1 = Bb + (size_t)(t + 1) * CONVCH;
            const float* C1 = Cb + (size_t)(t + 1) * CONVCH;
            #pragma unroll
            for (int i = 0; i < 4; i++) {
                nB[i] = *(const float4*)(B1 + i * 4);
                nC[i] = *(const float4*)(C1 + i * 4);
            }
            ndA = dAb[(t + 1) * NHEADS];
            ndt = dtb[(t + 1) * NHEADS];
            nx  = xb[(size_t)(t + 1) * CONVCH];
        }
        float dtx = cdt * cx;
        float acc = 0.f;
        #pragma unroll
        for (int i = 0; i < 4; i++) {
            float*       hv = hs + i * 4;
            const float* bp = (const float*)&cB[i];
            const float* cp = (const float*)&cC[i];
            #pragma unroll
            for (int j = 0; j < 4; j++) {
                hv[j] = fmaf(cdA, hv[j], dtx * bp[j]);
                acc   = fmaf(hv[j], cp[j], acc);
            }
        }
        acc += __shfl_down_sync(0xffffffffu, acc, 4, 8);
        acc += __shfl_down_sync(0xffffffffu, acc, 2, 8);
        acc += __shfl_down_sync(0xffffffffu, acc, 1, 8);
        if (sub == 0) yb[(size_t)t * DINNER] = acc + Dh * cx;
    }
}

// ---------------- 6) gate (y * silu(z)) + RMSNorm ---------------------------
__global__ void __launch_bounds__(256) gate_kernel(const float* __restrict__ norm_w) {
    __shared__ float red[32];
    int row = blockIdx.x;
    const float* zr = g_zx + (size_t)row * DPROJP;   // z = first 1536 cols
    float* yr = g_y + (size_t)row * DINNER;
    float g[6], ss = 0.f;
    #pragma unroll
    for (int i = 0; i < 6; i++) {
        int c = threadIdx.x + i * 256;
        float z = zr[c];
        float y = yr[c];
        float gv = y * (z / (1.f + expf(-z)));
        g[i] = gv;
        ss += gv * gv;
    }
    float tot = block_reduce_sum(ss, red);
    float inv = rsqrtf(tot / DINNER + EPSV);
    #pragma unroll
    for (int i = 0; i < 6; i++) {
        int c = threadIdx.x + i * 256;
        yr[c] = g[i] * inv * norm_w[c];
    }
}

// ---------------- launcher ---------------------------------------------------
extern "C" void kernel_launch(void* const* d_in, const int* in_sizes, int n_in,
                              void* d_out, int out_size) {
    const float* x       = (const float*)d_in[0];
    const float* ln_w    = (const float*)d_in[1];
    const float* ln_b    = (const float*)d_in[2];
    const float* W_in    = (const float*)d_in[3];
    const float* conv_w  = (const float*)d_in[4];
    const float* conv_b  = (const float*)d_in[5];
    const float* A_log   = (const float*)d_in[6];
    const float* Dv      = (const float*)d_in[7];
    const float* dt_bias = (const float*)d_in[8];
    const float* norm_w  = (const float*)d_in[9];
    const float* W_out   = (const float*)d_in[10];
    float* out = (float*)d_out;

    float *pu, *pzx, *py;
    cudaGetSymbolAddress((void**)&pu,  g_u);
    cudaGetSymbolAddress((void**)&pzx, g_zx);
    cudaGetSymbolAddress((void**)&py,  g_y);

    ln_kernel<<<NBT, 256>>>(x, ln_w, ln_b);

    // GEMM1: [16384x768] @ [768x3352] -> padded [16384x3456]
    dim3 g1(DPROJP / 128, NBT / 128);   // 27 x 128
    gemm_tf32<true, false><<<g1, 256>>>(pu, W_in, pzx, nullptr,
                                        NBT, DPROJ, DPROJP, DMODEL);

    conv_kernel<<<(NBT * CONVCH + 255) / 256, 256>>>(conv_w, conv_b);
    dt_kernel<<<(NBT * NHEADS + 255) / 256, 256>>>(dt_bias, A_log);

    scan_kernel<<<BSZ * NHEADS, 512>>>(Dv);

    gate_kernel<<<NBT, 256>>>(norm_w);

    // GEMM2: [16384x1536] @ [1536x768] + x -> out [16384x768]
    dim3 g2(DMODEL / 128, NBT / 128);   // 6 x 128
    gemm_tf32<false, true><<<g2, 256>>>(py, W_out, out, x,
                                        NBT, DMODEL, DMODEL, DINNER);
}